// round 16
// baseline (speedup 1.0000x reference)
#include <cuda_runtime.h>
#include <cuda_bf16.h>
#include <cstdint>
#include <math.h>

// ---------------------------------------------------------------------------
// ann2_snn1 — bit-faithful emulation of the JAX/XLA-CPU reference (verified
// rel_err == 0.0). Numerics contract (must not change):
//  * every dot product: ONE f32 accumulator, strictly ascending k, __fmaf_rn
//  * elementwise ops: separate f32 rounds in reference order
//  * logistic = 0.5 + 0.5*tanh(0.5x) with XLA's rational tanh
// ---------------------------------------------------------------------------

#define BATCH 1024
#define HID   500
#define NIN   784
#define NOUT  10
#define TLEN  100
#define TCH   25            // timesteps per scan chunk block
#define NCHUNK 4

__device__ float g_h[BATCH * HID];
__device__ float g_drive[BATCH * HID];
__device__ float g_cur[BATCH * TLEN * NOUT];   // [b][t][j] pre-bias dots

#define A1F ((float)1.1466802242428472)    // exp(-1/4)+exp(-1)
#define A2F ((float)-0.28650479686019009)  // -exp(-1/4)*exp(-1)
#define SGF ((float)0.77880078307140487)   // exp(-1/4)

__device__ __forceinline__ float xla_tanh_f32(float x)
{
    const float kMax = 7.90531110763549805f;
    float xc = fminf(fmaxf(x, -kMax), kMax);
    float x2 = __fmul_rn(xc, xc);
    float p = -2.76076847742355e-16f;
    p = __fadd_rn(__fmul_rn(p, x2), 2.00018790482477e-13f);
    p = __fadd_rn(__fmul_rn(p, x2), -8.60467152213735e-11f);
    p = __fadd_rn(__fmul_rn(p, x2), 5.12229709037114e-08f);
    p = __fadd_rn(__fmul_rn(p, x2), 1.48572235717979e-05f);
    p = __fadd_rn(__fmul_rn(p, x2), 6.37261928875436e-04f);
    p = __fadd_rn(__fmul_rn(p, x2), 4.89352455891786e-03f);
    float num = __fmul_rn(xc, p);
    float q = 1.19825839466702e-06f;
    q = __fadd_rn(__fmul_rn(q, x2), 1.18534705686654e-04f);
    q = __fadd_rn(__fmul_rn(q, x2), 2.26843463243900e-03f);
    q = __fadd_rn(__fmul_rn(q, x2), 4.89352518554385e-03f);
    float r = __fdiv_rn(num, q);
    return (fabsf(x) < 0.0004f) ? x : r;
}

__device__ __forceinline__ float xla_sigmoid(float x)
{
    float t = xla_tanh_f32(__fmul_rn(0.5f, x));
    return __fadd_rn(0.5f, __fmul_rn(0.5f, t));
}

// ---- cp.async helpers ----
__device__ __forceinline__ void cp_async16(unsigned int smem_dst,
                                           const void* gsrc, int src_bytes)
{
    asm volatile("cp.async.cg.shared.global [%0], [%1], 16, %2;"
                 :: "r"(smem_dst), "l"(gsrc), "r"(src_bytes));
}
__device__ __forceinline__ void cp_commit()
{
    asm volatile("cp.async.commit_group;");
}
template<int N>
__device__ __forceinline__ void cp_wait()
{
    asm volatile("cp.async.wait_group %0;" :: "n"(N));
}

// ---------------------------------------------------------------------------
// cp.async 4-stage pipelined SGEMM (R14 winner — unchanged).
// ---------------------------------------------------------------------------
#define BM 64
#define BN 32
#define BK 16
#define NSTAGE 4
#define A_STRIDE 16
#define W_STRIDE 20
#define A_TILE (BM * A_STRIDE)
#define W_TILE (BN * W_STRIDE)

template<int ACT>
__global__ __launch_bounds__(128)
void gemm_bias_act(const float* __restrict__ A, const float* __restrict__ W,
                   const float* __restrict__ bias, float* __restrict__ C,
                   int M, int N, int K)
{
    __shared__ float As[NSTAGE][A_TILE];
    __shared__ float Ws[NSTAGE][W_TILE];

    const int tid = threadIdx.x;
    const int tx  = tid & 7;
    const int ty  = tid >> 3;
    const int bm  = blockIdx.y * BM;
    const int bn  = blockIdx.x * BN;

    const int T = (K + BK - 1) / BK;

    auto issue_stage = [&](int it) {
        const int s  = it & (NSTAGE - 1);
        const int kb = it * BK;
        unsigned int abase = (unsigned int)__cvta_generic_to_shared(&As[s][0]);
        unsigned int wbase = (unsigned int)__cvta_generic_to_shared(&Ws[s][0]);
        #pragma unroll
        for (int p = 0; p < 2; p++) {
            int idx = tid + p * 128;
            int m   = idx >> 2;
            int c   = idx & 3;
            int k0  = kb + c * 4;
            int rem = K - k0;
            int bytes = rem >= 4 ? 16 : (rem > 0 ? rem * 4 : 0);
            const float* src = A + (size_t)(bm + m) * K + (bytes ? k0 : 0);
            unsigned int dst = abase +
                (unsigned int)((m * A_STRIDE + ((c ^ ((m >> 2) & 3)) * 4)) * 4);
            cp_async16(dst, src, bytes);
        }
        {
            int n   = tid >> 2;
            int c   = tid & 3;
            int k0  = kb + c * 4;
            int wr  = bn + n;
            int rem = K - k0;
            int bytes = (wr < N) ? (rem >= 4 ? 16 : (rem > 0 ? rem * 4 : 0)) : 0;
            const float* src = W + (bytes ? ((size_t)wr * K + k0) : 0);
            unsigned int dst = wbase +
                (unsigned int)((n * W_STRIDE + ((c ^ ((n >> 3) & 3)) * 4)) * 4);
            cp_async16(dst, src, bytes);
        }
        cp_commit();
    };

    float acc[4][4] = {};

    issue_stage(0);
    if (T > 1) issue_stage(1);
    if (T > 2) issue_stage(2);

    const int asw = ty & 3;
    const int wsw = (tx >> 1) & 3;

    for (int it = 0; it < T; it++) {
        const int s = it & (NSTAGE - 1);
        if (it + 3 < T) issue_stage(it + 3);
        cp_wait<3>();
        __syncthreads();

        #pragma unroll
        for (int c = 0; c < 4; c++) {
            float4 a4[4], w4[4];
            const int ac = (c ^ asw) * 4;
            const int wc = (c ^ wsw) * 4;
            #pragma unroll
            for (int i = 0; i < 4; i++)
                a4[i] = *(const float4*)&As[s][(ty * 4 + i) * A_STRIDE + ac];
            #pragma unroll
            for (int j = 0; j < 4; j++)
                w4[j] = *(const float4*)&Ws[s][(tx * 4 + j) * W_STRIDE + wc];
            #pragma unroll
            for (int kk = 0; kk < 4; kk++) {
                float a[4] = { kk == 0 ? a4[0].x : kk == 1 ? a4[0].y : kk == 2 ? a4[0].z : a4[0].w,
                               kk == 0 ? a4[1].x : kk == 1 ? a4[1].y : kk == 2 ? a4[1].z : a4[1].w,
                               kk == 0 ? a4[2].x : kk == 1 ? a4[2].y : kk == 2 ? a4[2].z : a4[2].w,
                               kk == 0 ? a4[3].x : kk == 1 ? a4[3].y : kk == 2 ? a4[3].z : a4[3].w };
                float w[4] = { kk == 0 ? w4[0].x : kk == 1 ? w4[0].y : kk == 2 ? w4[0].z : w4[0].w,
                               kk == 0 ? w4[1].x : kk == 1 ? w4[1].y : kk == 2 ? w4[1].z : w4[1].w,
                               kk == 0 ? w4[2].x : kk == 1 ? w4[2].y : kk == 2 ? w4[2].z : w4[2].w,
                               kk == 0 ? w4[3].x : kk == 1 ? w4[3].y : kk == 2 ? w4[3].z : w4[3].w };
                #pragma unroll
                for (int i = 0; i < 4; i++)
                    #pragma unroll
                    for (int j = 0; j < 4; j++)
                        acc[i][j] = __fmaf_rn(a[i], w[j], acc[i][j]);
            }
        }
        __syncthreads();
    }

    const int n0 = bn + tx * 4;
    if (n0 < N) {
        float bv0 = bias[n0 + 0], bv1 = bias[n0 + 1];
        float bv2 = bias[n0 + 2], bv3 = bias[n0 + 3];
        #pragma unroll
        for (int i = 0; i < 4; i++) {
            int m = bm + ty * 4 + i;
            float x0 = __fadd_rn(acc[i][0], bv0);
            float x1 = __fadd_rn(acc[i][1], bv1);
            float x2 = __fadd_rn(acc[i][2], bv2);
            float x3 = __fadd_rn(acc[i][3], bv3);
            if (ACT == 0) {
                x0 = fmaxf(x0, 0.f); x1 = fmaxf(x1, 0.f);
                x2 = fmaxf(x2, 0.f); x3 = fmaxf(x3, 0.f);
            } else {
                x0 = xla_sigmoid(x0); x1 = xla_sigmoid(x1);
                x2 = xla_sigmoid(x2); x3 = xla_sigmoid(x3);
            }
            *(float4*)&C[(size_t)m * N + n0] = make_float4(x0, x1, x2, x3);
        }
    }
}

// ---------------------------------------------------------------------------
// Scan chunk kernel: block = (b, chunk), 4096 blocks, 256 threads,
// smem = 25-row psp (50 KB) + w3 (20 KB) = 70 KB -> 3 blocks/SM.
//  phase1: 250 threads x 2 cols, recompute psp from t=0 (registers, exact),
//          store only this chunk's 25 rows.
//  phase2: 250 threads = (t, j): ONE strict ascending-k FMA chain each,
//          w3 from smem; writes g_cur coalesced (250 consecutive floats).
// ---------------------------------------------------------------------------
__global__ __launch_bounds__(256)
void scan_chunk_kernel(const float* __restrict__ w3g, float* __restrict__ curg)
{
    extern __shared__ float smem[];
    float* sp = smem;              // [TCH][HID]   50,000 B
    float* sw = smem + TCH * HID;  // [NOUT][HID]  20,000 B

    const int b   = blockIdx.x >> 2;
    const int ch  = blockIdx.x & 3;
    const int tlo = ch * TCH;
    const int tid = threadIdx.x;

    // stage w3 (coalesced float4)
    {
        const float4* src = (const float4*)w3g;
        float4* dst = (float4*)sw;
        for (int i = tid; i < (NOUT * HID) / 4; i += 256) dst[i] = src[i];
    }

    // phase1: psp recurrence from t=0; store rows [tlo, tlo+TCH)
    if (tid < 250) {
        const int k0 = tid, k1 = tid + 250;
        float d0 = g_drive[(size_t)b * HID + k0];
        float d1 = g_drive[(size_t)b * HID + k1];
        float p1a = 0.f, p2a = 0.f, p1b = 0.f, p2b = 0.f;
        for (int t = 0; t < tlo; t++) {       // warm-up, registers only
            float pa = __fadd_rn(__fadd_rn(__fmul_rn(A1F, p1a),
                                           __fmul_rn(A2F, p2a)), d0);
            float pb = __fadd_rn(__fadd_rn(__fmul_rn(A1F, p1b),
                                           __fmul_rn(A2F, p2b)), d1);
            p2a = p1a; p1a = pa;
            p2b = p1b; p1b = pb;
        }
        #pragma unroll 5
        for (int t = 0; t < TCH; t++) {
            float pa = __fadd_rn(__fadd_rn(__fmul_rn(A1F, p1a),
                                           __fmul_rn(A2F, p2a)), d0);
            float pb = __fadd_rn(__fadd_rn(__fmul_rn(A1F, p1b),
                                           __fmul_rn(A2F, p2b)), d1);
            sp[t * HID + k0] = pa;
            sp[t * HID + k1] = pb;
            p2a = p1a; p1a = pa;
            p2b = p1b; p1b = pb;
        }
    }
    __syncthreads();

    // phase2: (t, j) -> one ascending-k FMA chain
    if (tid < TCH * NOUT) {
        const int t = tid / NOUT;
        const int j = tid - t * NOUT;
        const float* pr = sp + t * HID;
        const float* wr = sw + j * HID;
        float a0 = 0.f;
        #pragma unroll 5
        for (int k = 0; k < HID; k += 4) {
            float4 pv = *(const float4*)(pr + k);
            float4 qv = *(const float4*)(wr + k);
            a0 = __fmaf_rn(pv.x, qv.x, a0);
            a0 = __fmaf_rn(pv.y, qv.y, a0);
            a0 = __fmaf_rn(pv.z, qv.z, a0);
            a0 = __fmaf_rn(pv.w, qv.w, a0);
        }
        curg[(size_t)b * (TLEN * NOUT) + tlo * NOUT + tid] = a0;
    }
}

// ---------------------------------------------------------------------------
// LIF slab kernel: 32 blocks x 320 threads; block handles 32 batch elements.
//  A: stage cur slab (32 x 100 x 10 floats = 128 KB) into smem, coalesced.
//  B: thread = (b_local, j): 100-step LIF chain from smem; spikes bit-packed
//     in registers (s in {0,1} -> exact).
//  C: unpack spikes into smem in out-layout [b][j][t]; coalesced store.
// ---------------------------------------------------------------------------
#define LIF_B 32
#define LIF_THREADS 320
#define SLAB_FLOATS (LIF_B * TLEN * NOUT)   // 32000

__global__ __launch_bounds__(LIF_THREADS)
void lif_slab_kernel(const float* __restrict__ curg,
                     const float* __restrict__ b3, float* __restrict__ out)
{
    extern __shared__ float slab[];        // 128,000 B
    const int tid = threadIdx.x;
    const int b0  = blockIdx.x * LIF_B;

    // A: coalesced load
    {
        const float4* src = (const float4*)(curg + (size_t)b0 * TLEN * NOUT);
        float4* dst = (float4*)slab;
        for (int i = tid; i < SLAB_FLOATS / 4; i += LIF_THREADS) dst[i] = src[i];
    }
    __syncthreads();

    // B: LIF chain (exact reference op order), spikes packed into 4 words
    const int bl = tid / NOUT;
    const int j  = tid - bl * NOUT;
    const float bb = b3[j];
    unsigned int bits[4] = {0, 0, 0, 0};
    {
        const float* base = slab + bl * (TLEN * NOUT) + j;
        float v = 0.f, s = 0.f;
        #pragma unroll 4
        for (int t = 0; t < TLEN; t++) {
            float cur = __fadd_rn(base[t * NOUT], bb);
            float t1  = __fmul_rn(SGF, v);
            float t2  = __fmul_rn(t1, __fsub_rn(1.f, s));
            float vn  = __fadd_rn(t2, cur);
            s = (vn >= 1.f) ? 1.f : 0.f;
            v = vn;
            if (s != 0.f) bits[t >> 5] |= (1u << (t & 31));
        }
    }
    __syncthreads();

    // C: unpack to out-layout [b_local][j][t] in smem
    {
        float* op = slab + bl * (TLEN * NOUT) + j * TLEN;
        for (int t = 0; t < TLEN; t++)
            op[t] = (bits[t >> 5] >> (t & 31)) & 1u ? 1.f : 0.f;
    }
    __syncthreads();

    // coalesced store
    {
        const float4* src = (const float4*)slab;
        float4* dst = (float4*)(out + (size_t)b0 * TLEN * NOUT);
        for (int i = tid; i < SLAB_FLOATS / 4; i += LIF_THREADS) dst[i] = src[i];
    }
}

#define SCAN_SMEM ((TCH * HID + NOUT * HID) * (int)sizeof(float))   // 70,000 B
#define LIF_SMEM  (SLAB_FLOATS * (int)sizeof(float))                // 128,000 B

extern "C" void kernel_launch(void* const* d_in, const int* in_sizes, int n_in,
                              void* d_out, int out_size)
{
    const float* inputs = (const float*)d_in[0];  // [1024, 784]
    const float* w1     = (const float*)d_in[1];  // [500, 784]
    const float* b1     = (const float*)d_in[2];  // [500]
    const float* w2     = (const float*)d_in[3];  // [500, 500]
    const float* b2     = (const float*)d_in[4];  // [500]
    const float* w3     = (const float*)d_in[5];  // [10, 500]
    const float* b3     = (const float*)d_in[6];  // [10]
    float* out          = (float*)d_out;          // [1024, 10, 100]

    float* h_buf;
    float* drive_buf;
    float* cur_buf;
    cudaGetSymbolAddress((void**)&h_buf, g_h);
    cudaGetSymbolAddress((void**)&drive_buf, g_drive);
    cudaGetSymbolAddress((void**)&cur_buf, g_cur);

    cudaFuncSetAttribute(scan_chunk_kernel,
                         cudaFuncAttributeMaxDynamicSharedMemorySize, SCAN_SMEM);
    cudaFuncSetAttribute(lif_slab_kernel,
                         cudaFuncAttributeMaxDynamicSharedMemorySize, LIF_SMEM);

    dim3 blk(128);
    dim3 grd((HID + BN - 1) / BN, BATCH / BM);   // 16 x 16 = 256 blocks
    gemm_bias_act<0><<<grd, blk>>>(inputs, w1, b1, h_buf, BATCH, HID, NIN);
    gemm_bias_act<1><<<grd, blk>>>(h_buf, w2, b2, drive_buf, BATCH, HID, HID);
    scan_chunk_kernel<<<BATCH * NCHUNK, 256, SCAN_SMEM>>>(w3, cur_buf);
    lif_slab_kernel<<<BATCH / LIF_B, LIF_THREADS, LIF_SMEM>>>(cur_buf, b3, out);
}